// round 8
// baseline (speedup 1.0000x reference)
#include <cuda_runtime.h>
#include <cuda_bf16.h>
#include <math.h>

#define BATCH   128
#define OUT_DIM 1024
#define IN_DIM  2048
#define MAXNNZ  64          // Poisson(8): P(row nnz > 64) ~ 1e-40 — safe cap
#define NSTRAIGHT 16        // unconditional gathers; sentinel-padded
#define GRID    128         // <= 148 SMs: ONE wave, co-residency guaranteed
#define THREADS 256

// Scratch (no allocations allowed anywhere):
__device__ int            g_cnt[OUT_DIM];
__device__ unsigned short g_idx[OUT_DIM][MAXNNZ];     // row-major, 128B rows
__device__ float          g_xT[(IN_DIM + 1) * BATCH]; // transposed x + sentinel row = 1.0f
__device__ unsigned long long g_bar;                  // monotonic barrier (replay-safe)

// Grid barrier: monotonic counter — each launch adds exactly GRID arrivals;
// target derived from the observed generation, so no reset across replays.
__device__ __forceinline__ void grid_sync() {
    __syncthreads();
    if (threadIdx.x == 0) {
        __threadfence();                               // release phase-1 writes
        unsigned long long old = atomicAdd(&g_bar, 1ULL);
        unsigned long long target = (old / GRID + 1ULL) * GRID;
        while (*(volatile unsigned long long*)&g_bar < target)
            __nanosleep(32);
        __threadfence();                               // acquire peers' writes
    }
    __syncthreads();
}

__global__ void __launch_bounds__(THREADS, 1)
bp_fused(const float* __restrict__ mask, const float* __restrict__ x,
         float* __restrict__ out) {
    __shared__ float smem[16 * 130];                   // 8320B, reused per phase
    const int tid  = threadIdx.x;
    const int lane = tid & 31;

    // ===== Phase 1a: index build — warp = one mask row, BITMASK compaction =====
    {
        const int o = blockIdx.x * 8 + (tid >> 5);
        const float4* row4 =
            reinterpret_cast<const float4*>(mask + (size_t)o * IN_DIM);

        // Per-lane 64-bit nonzero mask; peak live state = 8 float4 (32 regs).
        unsigned long long m = 0;
        #pragma unroll
        for (int half = 0; half < 2; half++) {
            float4 v[8];                               // 8 x 16B in flight
            #pragma unroll
            for (int u = 0; u < 8; u++)
                v[u] = row4[(half * 8 + u) * 32 + lane];
            #pragma unroll
            for (int u = 0; u < 8; u++) {
                unsigned bits = (unsigned)(v[u].x != 0.0f)
                              | ((unsigned)(v[u].y != 0.0f) << 1)
                              | ((unsigned)(v[u].z != 0.0f) << 2)
                              | ((unsigned)(v[u].w != 0.0f) << 3);
                m |= (unsigned long long)bits << ((half * 8 + u) * 4);
            }
        }

        int mycnt = __popcll(m);
        int scan  = mycnt;                             // inclusive warp scan
        #pragma unroll
        for (int d = 1; d < 32; d <<= 1) {
            int t = __shfl_up_sync(0xffffffffu, scan, d);
            if (lane >= d) scan += t;
        }
        const int total = __shfl_sync(0xffffffffu, scan, 31);
        int pos = scan - mycnt;                        // exclusive prefix

        while (m) {                                    // scatter set bits
            int bit = __ffsll((long long)m) - 1;
            m &= m - 1;
            int col = ((bit >> 2) * 32 + lane) * 4 + (bit & 3);
            if (pos < MAXNNZ)
                g_idx[o][pos] = (unsigned short)col;
            pos++;
        }
        for (int j = total + lane; j < NSTRAIGHT; j += 32)   // sentinel pad
            g_idx[o][j] = (unsigned short)IN_DIM;
        if (lane == 0) g_cnt[o] = total < MAXNNZ ? total : MAXNNZ;
    }
    __syncthreads();

    // ===== Phase 1b: transpose one 16-column strip of x =====
    {
        const int c0 = blockIdx.x * 16;                // 128 blocks x 16 = 2048
        const int c  = tid & 15;
        const int br = tid >> 4;                       // 0..15
        #pragma unroll
        for (int it = 0; it < 8; it++) {               // 128 batches
            const int b = br + 16 * it;
            smem[c * 130 + b] = x[(size_t)b * IN_DIM + c0 + c];
        }
        __syncthreads();
        const int b2 = tid & 127;
        const int cc = tid >> 7;                       // 0..1
        #pragma unroll
        for (int it = 0; it < 8; it++) {
            const int c3 = cc + 2 * it;
            g_xT[(size_t)(c0 + c3) * BATCH + b2] = smem[c3 * 130 + b2];
        }
        if (blockIdx.x == 0 && tid < BATCH)            // sentinel row -> 1.0f
            g_xT[(size_t)IN_DIM * BATCH + tid] = 1.0f;
    }

    // ========================== grid barrier ==========================
    grid_sync();

    // ===== Phase 2: check-node update (proven R4/R7 logic) =====
    // Tile = 32 o x 32 b; warp handles 4 o's x 32 batch-lanes. Indices
    // warp-uniform (broadcast); 64 coalesced 128B gathers in flight.
    float* s_t = smem;                                 // [32][33] view
    {
        const int o0 = (blockIdx.x >> 2) * 32;
        const int b0 = (blockIdx.x & 3) * 32;
        const int w  = tid >> 5;

        #pragma unroll
        for (int q = 0; q < 4; q++) {
            const int ol = w * 4 + q;                  // local o: 0..31
            const int o  = o0 + ol;

            const uint4* gi = reinterpret_cast<const uint4*>(&g_idx[o][0]);
            const uint4 A = gi[0], B = gi[1];          // uniform -> broadcast
            const int   n = g_cnt[o];

            int id[NSTRAIGHT];
            {
                const unsigned wd[8] = {A.x, A.y, A.z, A.w, B.x, B.y, B.z, B.w};
                #pragma unroll
                for (int k = 0; k < 8; k++) {
                    id[2 * k]     = wd[k] & 0xffffu;
                    id[2 * k + 1] = wd[k] >> 16;
                }
            }

            float v[NSTRAIGHT];
            #pragma unroll
            for (int k = 0; k < NSTRAIGHT; k++)
                v[k] = g_xT[(size_t)id[k] * BATCH + b0 + lane];

            float p = (((v[0]  * v[1])  * (v[2]  * v[3])) *
                       ((v[4]  * v[5])  * (v[6]  * v[7]))) *
                      (((v[8]  * v[9])  * (v[10] * v[11])) *
                       ((v[12] * v[13]) * (v[14] * v[15])));

            #pragma unroll 1
            for (int j = NSTRAIGHT; j < n; j++)        // warp-uniform, rare
                p *= g_xT[(size_t)g_idx[o][j] * BATCH + b0 + lane];

            const float lim = 1.0f - 1e-7f;            // folds to 0.99999988f
            p = fminf(fmaxf(p, -lim), lim);
            s_t[ol * 33 + lane] = __logf((1.0f + p) / (1.0f - p));
        }
        __syncthreads();

        #pragma unroll
        for (int e = 0; e < 4; e++) {                  // coalesced stores
            const int idx = tid + e * 256;
            const int r = idx >> 5;                    // batch local
            const int c = idx & 31;                    // o local
            out[(size_t)(b0 + r) * OUT_DIM + o0 + c] = s_t[c * 33 + r];
        }
    }
}

// ---------------------------------------------------------------------------
extern "C" void kernel_launch(void* const* d_in, const int* in_sizes, int n_in,
                              void* d_out, int out_size) {
    const float* x    = (const float*)d_in[0];   // [128, 2048]
    const float* mask = (const float*)d_in[1];   // [1024, 2048]
    float*       out  = (float*)d_out;           // [128, 1024]

    bp_fused<<<GRID, THREADS>>>(mask, x, out);   // single launch, single wave
}